// round 12
// baseline (speedup 1.0000x reference)
#include <cuda_runtime.h>
#include <cstdint>

#define NROWS 65536
#define D 64
#define K 1024
#define BLOCK 256
#define NCTAS (NROWS / BLOCK)   // 256
#define CH 256
#define NCH (K / CH)            // 4
#define TAU 5e-4f
#define RW 8
#define SE 130048.0f            // 127*1024

// Static scratch (no allocations).
__device__ uint4  g_emb8[K * 4];      // t-major permuted int8 codebook (64B/entry)
__device__ float  g_ee[K];            // exact fp32 ||e||^2
__device__ uint4  g_z8[NROWS * 4];    // t-major permuted int8 z rows (4 MB)
__device__ float  g_isz[NROWS];       // 2/(Se*Sz_row)
__device__ double g_acc;
__device__ int    g_rescore_n;
__device__ int    g_rescore_rows[NROWS];

__device__ __forceinline__ uint32_t pk4(int a, int b, int c, int d) {
    return (uint32_t)(a & 255) | ((uint32_t)(b & 255) << 8) |
           ((uint32_t)(c & 255) << 16) | ((uint32_t)(d & 255) << 24);
}
__device__ __forceinline__ void imma16832(int& c0, int& c1, int& c2, int& c3,
                                          uint32_t a0, uint32_t a1, uint32_t a2, uint32_t a3,
                                          uint32_t b0, uint32_t b1) {
    asm volatile("mma.sync.aligned.m16n8k32.row.col.s32.s8.s8.s32 "
                 "{%0,%1,%2,%3}, {%4,%5,%6,%7}, {%8,%9}, {%0,%1,%2,%3};"
                 : "+r"(c0), "+r"(c1), "+r"(c2), "+r"(c3)
                 : "r"(a0), "r"(a1), "r"(a2), "r"(a3), "r"(b0), "r"(b1));
}
// Index in low 10 mantissa bits; perturbation <= ~6e-6 << TAU.
__device__ __forceinline__ float packd(float d, uint32_t e) {
    return __uint_as_float((__float_as_uint(d) & 0xFFFFFC00u) | e);
}
__device__ __forceinline__ void upd(float& m1, float& m2, float f) {
    float mx = fmaxf(m1, f);
    m1 = fminf(m1, f);
    m2 = fminf(m2, mx);
}
__device__ __forceinline__ void red4(float& m1, float& m2) {
    #pragma unroll
    for (int off = 1; off <= 2; off <<= 1) {
        float om1 = __shfl_xor_sync(0xffffffffu, m1, off);
        float om2 = __shfl_xor_sync(0xffffffffu, m2, off);
        m2 = fminf(fminf(m2, om2), fmaxf(m1, om1));
        m1 = fminf(m1, om1);
    }
}

// Codebook prep: exact ||e||^2 + int8 quant (Se) + t-major permute.
__global__ void vq_pre_emb_kernel(const float* __restrict__ emb) {
    int k = blockIdx.x * blockDim.x + threadIdx.x;
    if (k == 0) { g_acc = 0.0; g_rescore_n = 0; }
    if (k < K) {
        const float* e = emb + k * D;
        float s = 0.f;
        int q[64];
        #pragma unroll
        for (int j = 0; j < 64; ++j) {
            float v = e[j];
            s += v * v;
            q[j] = __float2int_rn(v * SE);
        }
        g_ee[k] = s;
        #pragma unroll
        for (int t = 0; t < 4; ++t) {
            uint4 d;
            d.x = pk4(q[4*t],    q[4*t+1],    q[4*t+2],    q[4*t+3]);
            d.y = pk4(q[16+4*t], q[16+4*t+1], q[16+4*t+2], q[16+4*t+3]);
            d.z = pk4(q[32+4*t], q[32+4*t+1], q[32+4*t+2], q[32+4*t+3]);
            d.w = pk4(q[48+4*t], q[48+4*t+1], q[48+4*t+2], q[48+4*t+3]);
            g_emb8[k * 4 + t] = d;
        }
    }
}

// z prep: per-row scale + int8 quant + t-major permute.
__global__ void vq_pre_z_kernel(const float* __restrict__ z) {
    int r = blockIdx.x * blockDim.x + threadIdx.x;
    if (r >= NROWS) return;
    const float4* zp = (const float4*)z + (size_t)r * 16;
    float v[64];
    float m = 0.f;
    #pragma unroll
    for (int j = 0; j < 16; ++j) {
        float4 u = zp[j];
        v[4*j] = u.x; v[4*j+1] = u.y; v[4*j+2] = u.z; v[4*j+3] = u.w;
        m = fmaxf(m, fmaxf(fmaxf(fabsf(u.x), fabsf(u.y)),
                           fmaxf(fabsf(u.z), fabsf(u.w))));
    }
    m = fmaxf(m, 1e-20f);
    float sz = 127.f / m;
    g_isz[r] = 2.f * m / (127.f * SE);
    int q[64];
    #pragma unroll
    for (int j = 0; j < 64; ++j) q[j] = __float2int_rn(v[j] * sz);
    #pragma unroll
    for (int t = 0; t < 4; ++t) {
        uint4 d;
        d.x = pk4(q[4*t],    q[4*t+1],    q[4*t+2],    q[4*t+3]);
        d.y = pk4(q[16+4*t], q[16+4*t+1], q[16+4*t+2], q[16+4*t+3]);
        d.z = pk4(q[32+4*t], q[32+4*t+1], q[32+4*t+2], q[32+4*t+3]);
        d.w = pk4(q[48+4*t], q[48+4*t+1], q[48+4*t+2], q[48+4*t+3]);
        g_z8[r * 4 + t] = d;
    }
}

__global__ __launch_bounds__(BLOCK)
void vq_main_kernel(const float* __restrict__ z,
                    const float* __restrict__ emb,
                    float* __restrict__ out) {
    __shared__ uint4  s_b[CH * 4];     // 16 KB int8 codebook chunk (permuted)
    __shared__ float  s_ee[K];
    __shared__ float  s_m1[BLOCK], s_m2[BLOCK];
    __shared__ double s_red[BLOCK / 32];

    const int tid   = threadIdx.x;
    const int warp  = tid >> 5;
    const int lane  = tid & 31;
    const int g     = lane >> 2;
    const int t     = lane & 3;
    const int rbase = blockIdx.x * BLOCK;
    const int wrow  = rbase + warp * 32;

    #pragma unroll
    for (int i = 0; i < K / BLOCK; ++i)
        s_ee[i * BLOCK + tid] = g_ee[i * BLOCK + tid];

    // A fragments: 4 rows per lane (g, g+8, g+16, g+24), permuted int8.
    uint4 Q0 = g_z8[(size_t)(wrow + g) * 4 + t];
    uint4 Q1 = g_z8[(size_t)(wrow + g + 8) * 4 + t];
    uint4 Q2 = g_z8[(size_t)(wrow + g + 16) * 4 + t];
    uint4 Q3 = g_z8[(size_t)(wrow + g + 24) * 4 + t];
    float isz0 = g_isz[wrow + g];
    float isz1 = g_isz[wrow + g + 8];
    float isz2 = g_isz[wrow + g + 16];
    float isz3 = g_isz[wrow + g + 24];

    float u0m1 = 3.0e38f, u0m2 = 3.0e38f, l0m1 = 3.0e38f, l0m2 = 3.0e38f;
    float u1m1 = 3.0e38f, u1m2 = 3.0e38f, l1m1 = 3.0e38f, l1m2 = 3.0e38f;

    for (int ch = 0; ch < NCH; ++ch) {
        __syncthreads();
        {   // Stage 256 entries: 1 entry (64B) per thread, coalesced.
            const uint4* src = g_emb8 + (size_t)(ch * CH + tid) * 4;
            uint4* dst = s_b + tid * 4;
            dst[0] = src[0]; dst[1] = src[1]; dst[2] = src[2]; dst[3] = src[3];
        }
        __syncthreads();

        for (int nt = 0; nt < CH / 8; ++nt) {
            const int nbl = nt * 8;
            const int nb  = ch * CH + nbl;
            uint4 E = s_b[(nbl + g) * 4 + t];   // conflict-free LDS.128

            int c00 = 0, c01 = 0, c02 = 0, c03 = 0;
            int c10 = 0, c11 = 0, c12 = 0, c13 = 0;
            // tile0 (rows g, g+8): k 0..31 then 32..63
            imma16832(c00, c01, c02, c03, Q0.x, Q1.x, Q0.y, Q1.y, E.x, E.y);
            imma16832(c00, c01, c02, c03, Q0.z, Q1.z, Q0.w, Q1.w, E.z, E.w);
            // tile1 (rows g+16, g+24)
            imma16832(c10, c11, c12, c13, Q2.x, Q3.x, Q2.y, Q3.y, E.x, E.y);
            imma16832(c10, c11, c12, c13, Q2.z, Q3.z, Q2.w, Q3.w, E.z, E.w);

            float2 ee = *(const float2*)(s_ee + nb + 2 * t);
            uint32_t e0 = nb + 2 * t, e1 = e0 + 1;
            upd(u0m1, u0m2, packd(fmaf(-isz0, (float)c00, ee.x), e0));
            upd(u0m1, u0m2, packd(fmaf(-isz0, (float)c01, ee.y), e1));
            upd(l0m1, l0m2, packd(fmaf(-isz1, (float)c02, ee.x), e0));
            upd(l0m1, l0m2, packd(fmaf(-isz1, (float)c03, ee.y), e1));
            upd(u1m1, u1m2, packd(fmaf(-isz2, (float)c10, ee.x), e0));
            upd(u1m1, u1m2, packd(fmaf(-isz2, (float)c11, ee.y), e1));
            upd(l1m1, l1m2, packd(fmaf(-isz3, (float)c12, ee.x), e0));
            upd(l1m1, l1m2, packd(fmaf(-isz3, (float)c13, ee.y), e1));
        }
    }

    red4(u0m1, u0m2); red4(l0m1, l0m2); red4(u1m1, u1m2); red4(l1m1, l1m2);
    if (t == 0) {
        int lr = warp * 32 + g;
        s_m1[lr]      = u0m1; s_m2[lr]      = u0m2;
        s_m1[lr + 8]  = l0m1; s_m2[lr + 8]  = l0m2;
        s_m1[lr + 16] = u1m1; s_m2[lr + 16] = u1m2;
        s_m1[lr + 24] = l1m1; s_m2[lr + 24] = l1m2;
    }
    __syncthreads();

    // Epilogue: one thread per row.
    const int row = rbase + tid;
    float m1 = s_m1[tid], m2 = s_m2[tid];
    int   idx1 = (int)(__float_as_uint(m1) & 1023u);
    const float4* zp = (const float4*)z + (size_t)row * 16;

    double lacc = 0.0;
    if (m2 - m1 < TAU) {
        int pos = atomicAdd(&g_rescore_n, 1);
        g_rescore_rows[pos] = row;
    } else {
        const float4* eb = (const float4*)emb + (size_t)idx1 * 16;
        float4* op = (float4*)out + (size_t)row * 16;
        #pragma unroll
        for (int j = 0; j < 16; ++j) {
            float4 q = eb[j];
            float4 zv = zp[j];
            op[j] = q;
            float dx = q.x - zv.x, dy = q.y - zv.y;
            float dz = q.z - zv.z, dw = q.w - zv.w;
            lacc += (double)dx * dx + (double)dy * dy
                  + (double)dz * dz + (double)dw * dw;
        }
    }
    #pragma unroll
    for (int off = 16; off; off >>= 1)
        lacc += __shfl_down_sync(0xffffffffu, lacc, off);
    if (lane == 0) s_red[warp] = lacc;
    __syncthreads();
    if (tid == 0) {
        double b = 0.0;
        #pragma unroll
        for (int i = 0; i < BLOCK / 32; ++i) b += s_red[i];
        atomicAdd(&g_acc, b);
    }
}

// Exact fp32 full rescan for near-tie rows (R1 arithmetic order; matched ref).
__global__ __launch_bounds__(256)
void vq_rescore_kernel(const float* __restrict__ z,
                       const float* __restrict__ emb,
                       float* __restrict__ out) {
    __shared__ float s_emb[128 * 69];
    __shared__ float s_zrow[RW * 64];
    __shared__ int   s_rows[RW];

    int nre  = g_rescore_n;
    int base = blockIdx.x * RW;
    if (base >= nre) return;

    int tid = threadIdx.x;
    int w = tid >> 5, l = tid & 31;

    if (tid < RW)
        s_rows[tid] = (base + tid < nre) ? g_rescore_rows[base + tid] : -1;
    __syncthreads();

    if (tid < RW * 16) {
        int rw = tid >> 4, j = tid & 15;
        int r = s_rows[rw];
        if (r >= 0)
            *(float4*)(s_zrow + rw * 64 + j * 4) = ((const float4*)z)[(size_t)r * 16 + j];
    }
    __syncthreads();

    int myrow = s_rows[w];

    float zz = 0.f;
    if (myrow >= 0)
        for (int i = 0; i < 64; ++i) { float v = s_zrow[w * 64 + i]; zz += v * v; }

    float dmin = 3.4e38f;
    int   best = 0;

    for (int tt = 0; tt < K / 128; ++tt) {
        __syncthreads();
        for (int f = tid; f < 128 * 16; f += 256) {
            int e = f >> 4, j = f & 15;
            float4 v = ((const float4*)emb)[(size_t)(tt * 128 + e) * 16 + j];
            float* dst = s_emb + e * 69 + j * 4;
            dst[0] = v.x; dst[1] = v.y; dst[2] = v.z; dst[3] = v.w;
        }
        __syncthreads();
        if (myrow >= 0) {
            #pragma unroll
            for (int s = 0; s < 4; ++s) {
                int el = s * 32 + l;
                const float* e = s_emb + el * 69;
                float ze = 0.f;
                for (int i = 0; i < 64; ++i) ze += s_zrow[w * 64 + i] * e[i];
                int ge = tt * 128 + el;
                float d = (zz - 2.0f * ze) + g_ee[ge];
                if (d < dmin) { dmin = d; best = ge; }
            }
        }
    }

    #pragma unroll
    for (int off = 16; off; off >>= 1) {
        float od = __shfl_down_sync(0xffffffffu, dmin, off);
        int   oi = __shfl_down_sync(0xffffffffu, best, off);
        if (od < dmin || (od == dmin && oi < best)) { dmin = od; best = oi; }
    }

    if (myrow >= 0 && l == 0) {
        const float4* eb = (const float4*)emb + (size_t)best * 16;
        float4* op = (float4*)out + (size_t)myrow * 16;
        double lacc = 0.0;
        for (int j = 0; j < 16; ++j) {
            float4 q = eb[j];
            float zx = s_zrow[w * 64 + j * 4 + 0];
            float zy = s_zrow[w * 64 + j * 4 + 1];
            float zzv = s_zrow[w * 64 + j * 4 + 2];
            float zw = s_zrow[w * 64 + j * 4 + 3];
            op[j] = q;
            float dx = q.x - zx, dy = q.y - zy, dz = q.z - zzv, dw = q.w - zw;
            lacc += (double)dx * dx + (double)dy * dy
                  + (double)dz * dz + (double)dw * dw;
        }
        atomicAdd(&g_acc, lacc);
    }
}

__global__ void vq_fin_kernel(float* __restrict__ out, int out_size) {
    if (out_size > NROWS * D) {
        out[NROWS * D] = (float)(1.25 * g_acc / (double)((long long)NROWS * D));
    }
}

extern "C" void kernel_launch(void* const* d_in, const int* in_sizes, int n_in,
                              void* d_out, int out_size) {
    const float* z   = (const float*)d_in[0];
    const float* emb = (const float*)d_in[1];
    if (n_in >= 2 && in_sizes[0] == K * D && in_sizes[1] == NROWS * D) {
        z   = (const float*)d_in[1];
        emb = (const float*)d_in[0];
    }
    float* out = (float*)d_out;

    vq_pre_emb_kernel<<<8, 128>>>(emb);
    vq_pre_z_kernel<<<NROWS / 256, 256>>>(z);
    vq_main_kernel<<<NCTAS, BLOCK>>>(z, emb, out);
    vq_rescore_kernel<<<NROWS / RW, 256>>>(z, emb, out);
    vq_fin_kernel<<<1, 1>>>(out, out_size);
}

// round 13
// speedup vs baseline: 2.1315x; 2.1315x over previous
#include <cuda_runtime.h>
#include <cstdint>

#define NROWS 65536
#define D 64
#define K 1024
#define BLOCK 256
#define NCTAS (NROWS / BLOCK)   // 256
#define CH 256
#define NCH (K / CH)            // 4
#define TAU 5e-4f
#define RW 16
#define SE 130048.0f            // 127*1024

// Static scratch (no allocations).
__device__ uint4  g_emb8[K * 4];      // t-major permuted int8 codebook (64B/entry)
__device__ float  g_ee[K];            // exact fp32 ||e||^2 (R1 sequential order)
__device__ uint4  g_z8[NROWS * 4];    // t-major permuted int8 z rows
__device__ float  g_isz[NROWS];       // 2/(Se*Sz_row)
__device__ double g_acc;
__device__ int    g_rescore_n;
__device__ int    g_rescore_rows[NROWS];

__device__ __forceinline__ uint32_t pk4(int a, int b, int c, int d) {
    return (uint32_t)(a & 255) | ((uint32_t)(b & 255) << 8) |
           ((uint32_t)(c & 255) << 16) | ((uint32_t)(d & 255) << 24);
}
__device__ __forceinline__ void imma16832(int& c0, int& c1, int& c2, int& c3,
                                          uint32_t a0, uint32_t a1, uint32_t a2, uint32_t a3,
                                          uint32_t b0, uint32_t b1) {
    asm volatile("mma.sync.aligned.m16n8k32.row.col.s32.s8.s8.s32 "
                 "{%0,%1,%2,%3}, {%4,%5,%6,%7}, {%8,%9}, {%0,%1,%2,%3};"
                 : "+r"(c0), "+r"(c1), "+r"(c2), "+r"(c3)
                 : "r"(a0), "r"(a1), "r"(a2), "r"(a3), "r"(b0), "r"(b1));
}
__device__ __forceinline__ float packd(float d, uint32_t e) {
    return __uint_as_float((__float_as_uint(d) & 0xFFFFFC00u) | e);
}
// Branch-free running top-4 (m1..m3 carry indices in mantissa; m4 for validation).
__device__ __forceinline__ void upd4(float& m1, float& m2, float& m3, float& m4, float f) {
    float x1 = fmaxf(m1, f); m1 = fminf(m1, f);
    float x2 = fmaxf(m2, x1); m2 = fminf(m2, x1);
    float x3 = fmaxf(m3, x2); m3 = fminf(m3, x2);
    m4 = fminf(m4, x3);
}
// Merge sorted 4-tuples across 4 lanes (kth-of-two-sorted-arrays formula).
__device__ __forceinline__ void red4x4(float& m1, float& m2, float& m3, float& m4) {
    #pragma unroll
    for (int off = 1; off <= 2; off <<= 1) {
        float o1 = __shfl_xor_sync(0xffffffffu, m1, off);
        float o2 = __shfl_xor_sync(0xffffffffu, m2, off);
        float o3 = __shfl_xor_sync(0xffffffffu, m3, off);
        float o4 = __shfl_xor_sync(0xffffffffu, m4, off);
        float n1 = fminf(m1, o1);
        float n2 = fminf(fminf(m2, o2), fmaxf(m1, o1));
        float n3 = fminf(fminf(m3, o3), fminf(fmaxf(m2, o1), fmaxf(m1, o2)));
        float n4 = fminf(fminf(m4, o4),
                   fminf(fminf(fmaxf(m3, o1), fmaxf(m1, o3)), fmaxf(m2, o2)));
        m1 = n1; m2 = n2; m3 = n3; m4 = n4;
    }
}

__global__ void vq_pre_emb_kernel(const float* __restrict__ emb) {
    int k = blockIdx.x * blockDim.x + threadIdx.x;
    if (k == 0) { g_acc = 0.0; g_rescore_n = 0; }
    if (k < K) {
        const float* e = emb + k * D;
        float s = 0.f;
        int q[64];
        #pragma unroll
        for (int j = 0; j < 64; ++j) {
            float v = e[j];
            s += v * v;
            q[j] = __float2int_rn(v * SE);
        }
        g_ee[k] = s;
        #pragma unroll
        for (int t = 0; t < 4; ++t) {
            uint4 d;
            d.x = pk4(q[4*t],    q[4*t+1],    q[4*t+2],    q[4*t+3]);
            d.y = pk4(q[16+4*t], q[16+4*t+1], q[16+4*t+2], q[16+4*t+3]);
            d.z = pk4(q[32+4*t], q[32+4*t+1], q[32+4*t+2], q[32+4*t+3]);
            d.w = pk4(q[48+4*t], q[48+4*t+1], q[48+4*t+2], q[48+4*t+3]);
            g_emb8[k * 4 + t] = d;
        }
    }
}

__global__ void vq_pre_z_kernel(const float* __restrict__ z) {
    int r = blockIdx.x * blockDim.x + threadIdx.x;
    if (r >= NROWS) return;
    const float4* zp = (const float4*)z + (size_t)r * 16;
    float v[64];
    float m = 0.f;
    #pragma unroll
    for (int j = 0; j < 16; ++j) {
        float4 u = zp[j];
        v[4*j] = u.x; v[4*j+1] = u.y; v[4*j+2] = u.z; v[4*j+3] = u.w;
        m = fmaxf(m, fmaxf(fmaxf(fabsf(u.x), fabsf(u.y)),
                           fmaxf(fabsf(u.z), fabsf(u.w))));
    }
    m = fmaxf(m, 1e-20f);
    float sz = 127.f / m;
    g_isz[r] = 2.f * m / (127.f * SE);
    int q[64];
    #pragma unroll
    for (int j = 0; j < 64; ++j) q[j] = __float2int_rn(v[j] * sz);
    #pragma unroll
    for (int t = 0; t < 4; ++t) {
        uint4 d;
        d.x = pk4(q[4*t],    q[4*t+1],    q[4*t+2],    q[4*t+3]);
        d.y = pk4(q[16+4*t], q[16+4*t+1], q[16+4*t+2], q[16+4*t+3]);
        d.z = pk4(q[32+4*t], q[32+4*t+1], q[32+4*t+2], q[32+4*t+3]);
        d.w = pk4(q[48+4*t], q[48+4*t+1], q[48+4*t+2], q[48+4*t+3]);
        g_z8[r * 4 + t] = d;
    }
}

// Exact fp32 distance for one (row, entry) pair, R1 arithmetic ordering.
__device__ __forceinline__ float exact_d(const float4* zp, const float* __restrict__ emb,
                                         float zz, float eek, int idx) {
    const float4* ev = (const float4*)(emb + (size_t)idx * D);
    float ze = 0.f;
    #pragma unroll
    for (int j = 0; j < 16; ++j) {
        float4 e = ev[j];
        float4 zv = zp[j];
        ze += zv.x * e.x; ze += zv.y * e.y;
        ze += zv.z * e.z; ze += zv.w * e.w;
    }
    return (zz - 2.0f * ze) + eek;
}

__global__ __launch_bounds__(BLOCK)
void vq_main_kernel(const float* __restrict__ z,
                    const float* __restrict__ emb,
                    float* __restrict__ out) {
    __shared__ uint4  s_b[CH * 4];     // 16 KB int8 codebook chunk (permuted)
    __shared__ float  s_ee[K];
    __shared__ float  s_m1[BLOCK], s_m2[BLOCK], s_m3[BLOCK], s_m4[BLOCK];
    __shared__ double s_red[BLOCK / 32];

    const int tid   = threadIdx.x;
    const int warp  = tid >> 5;
    const int lane  = tid & 31;
    const int g     = lane >> 2;
    const int t     = lane & 3;
    const int rbase = blockIdx.x * BLOCK;
    const int wrow  = rbase + warp * 32;

    #pragma unroll
    for (int i = 0; i < K / BLOCK; ++i)
        s_ee[i * BLOCK + tid] = g_ee[i * BLOCK + tid];

    uint4 Q0 = g_z8[(size_t)(wrow + g) * 4 + t];
    uint4 Q1 = g_z8[(size_t)(wrow + g + 8) * 4 + t];
    uint4 Q2 = g_z8[(size_t)(wrow + g + 16) * 4 + t];
    uint4 Q3 = g_z8[(size_t)(wrow + g + 24) * 4 + t];
    float isz0 = g_isz[wrow + g];
    float isz1 = g_isz[wrow + g + 8];
    float isz2 = g_isz[wrow + g + 16];
    float isz3 = g_isz[wrow + g + 24];

    float a1 = 3.0e38f, a2 = 3.0e38f, a3 = 3.0e38f, a4 = 3.0e38f;   // row g
    float b1 = 3.0e38f, b2 = 3.0e38f, b3 = 3.0e38f, b4 = 3.0e38f;   // row g+8
    float c1 = 3.0e38f, c2 = 3.0e38f, c3 = 3.0e38f, c4 = 3.0e38f;   // row g+16
    float d1 = 3.0e38f, d2 = 3.0e38f, d3 = 3.0e38f, d4 = 3.0e38f;   // row g+24

    for (int ch = 0; ch < NCH; ++ch) {
        __syncthreads();
        {
            const uint4* src = g_emb8 + (size_t)(ch * CH + tid) * 4;
            uint4* dst = s_b + tid * 4;
            dst[0] = src[0]; dst[1] = src[1]; dst[2] = src[2]; dst[3] = src[3];
        }
        __syncthreads();

        for (int nt = 0; nt < CH / 8; ++nt) {
            const int nbl = nt * 8;
            const int nb  = ch * CH + nbl;
            uint4 E = s_b[(nbl + g) * 4 + t];

            int c00 = 0, c01 = 0, c02 = 0, c03 = 0;
            int c10 = 0, c11 = 0, c12 = 0, c13 = 0;
            imma16832(c00, c01, c02, c03, Q0.x, Q1.x, Q0.y, Q1.y, E.x, E.y);
            imma16832(c00, c01, c02, c03, Q0.z, Q1.z, Q0.w, Q1.w, E.z, E.w);
            imma16832(c10, c11, c12, c13, Q2.x, Q3.x, Q2.y, Q3.y, E.x, E.y);
            imma16832(c10, c11, c12, c13, Q2.z, Q3.z, Q2.w, Q3.w, E.z, E.w);

            float2 ee = *(const float2*)(s_ee + nb + 2 * t);
            uint32_t e0 = nb + 2 * t, e1 = e0 + 1;
            upd4(a1, a2, a3, a4, packd(fmaf(-isz0, (float)c00, ee.x), e0));
            upd4(a1, a2, a3, a4, packd(fmaf(-isz0, (float)c01, ee.y), e1));
            upd4(b1, b2, b3, b4, packd(fmaf(-isz1, (float)c02, ee.x), e0));
            upd4(b1, b2, b3, b4, packd(fmaf(-isz1, (float)c03, ee.y), e1));
            upd4(c1, c2, c3, c4, packd(fmaf(-isz2, (float)c10, ee.x), e0));
            upd4(c1, c2, c3, c4, packd(fmaf(-isz2, (float)c11, ee.y), e1));
            upd4(d1, d2, d3, d4, packd(fmaf(-isz3, (float)c12, ee.x), e0));
            upd4(d1, d2, d3, d4, packd(fmaf(-isz3, (float)c13, ee.y), e1));
        }
    }

    red4x4(a1, a2, a3, a4); red4x4(b1, b2, b3, b4);
    red4x4(c1, c2, c3, c4); red4x4(d1, d2, d3, d4);
    if (t == 0) {
        int lr = warp * 32 + g;
        s_m1[lr]      = a1; s_m2[lr]      = a2; s_m3[lr]      = a3; s_m4[lr]      = a4;
        s_m1[lr + 8]  = b1; s_m2[lr + 8]  = b2; s_m3[lr + 8]  = b3; s_m4[lr + 8]  = b4;
        s_m1[lr + 16] = c1; s_m2[lr + 16] = c2; s_m3[lr + 16] = c3; s_m4[lr + 16] = c4;
        s_m1[lr + 24] = d1; s_m2[lr + 24] = d2; s_m3[lr + 24] = d3; s_m4[lr + 24] = d4;
    }
    __syncthreads();

    // Epilogue: one thread per row.
    const int row = rbase + tid;
    float m1 = s_m1[tid], m2 = s_m2[tid], m3 = s_m3[tid], m4 = s_m4[tid];
    const float4* zp = (const float4*)z + (size_t)row * 16;

    int winner = -1;
    if (m2 - m1 >= TAU) {
        winner = (int)(__float_as_uint(m1) & 1023u);   // R12-proven direct path
    } else if (m4 - m1 >= TAU) {
        // True argmin provably among top-3 approx candidates: exact fp32 duel.
        int i1 = (int)(__float_as_uint(m1) & 1023u);
        int i2 = (int)(__float_as_uint(m2) & 1023u);
        int i3 = (int)(__float_as_uint(m3) & 1023u);
        float zz = 0.f;
        #pragma unroll
        for (int j = 0; j < 16; ++j) {
            float4 zv = zp[j];
            zz += zv.x * zv.x; zz += zv.y * zv.y;
            zz += zv.z * zv.z; zz += zv.w * zv.w;
        }
        float e1 = exact_d(zp, emb, zz, s_ee[i1], i1);
        float e2 = exact_d(zp, emb, zz, s_ee[i2], i2);
        float e3 = exact_d(zp, emb, zz, s_ee[i3], i3);
        winner = i1; float wd = e1;
        if (e2 < wd || (e2 == wd && i2 < winner)) { wd = e2; winner = i2; }
        if (e3 < wd || (e3 == wd && i3 < winner)) { wd = e3; winner = i3; }
    }

    double lacc = 0.0;
    if (winner < 0) {
        int pos = atomicAdd(&g_rescore_n, 1);
        g_rescore_rows[pos] = row;
    } else {
        const float4* eb = (const float4*)emb + (size_t)winner * 16;
        float4* op = (float4*)out + (size_t)row * 16;
        #pragma unroll
        for (int j = 0; j < 16; ++j) {
            float4 q = eb[j];
            float4 zv = zp[j];
            op[j] = q;
            float dx = q.x - zv.x, dy = q.y - zv.y;
            float dz = q.z - zv.z, dw = q.w - zv.w;
            lacc += (double)dx * dx + (double)dy * dy
                  + (double)dz * dz + (double)dw * dw;
        }
    }
    #pragma unroll
    for (int off = 16; off; off >>= 1)
        lacc += __shfl_down_sync(0xffffffffu, lacc, off);
    if (lane == 0) s_red[warp] = lacc;
    __syncthreads();
    if (tid == 0) {
        double b = 0.0;
        #pragma unroll
        for (int i = 0; i < BLOCK / 32; ++i) b += s_red[i];
        atomicAdd(&g_acc, b);
    }
}

// Exact fp32 full rescan fallback. 16 rows/block (2 per warp) to amortize tiles.
__global__ __launch_bounds__(256)
void vq_rescore_kernel(const float* __restrict__ z,
                       const float* __restrict__ emb,
                       float* __restrict__ out) {
    __shared__ float s_emb[128 * 69];
    __shared__ float s_zrow[RW * 64];
    __shared__ int   s_rows[RW];

    int nre  = g_rescore_n;
    int base = blockIdx.x * RW;
    if (base >= nre) return;

    int tid = threadIdx.x;
    int w = tid >> 5, l = tid & 31;

    if (tid < RW)
        s_rows[tid] = (base + tid < nre) ? g_rescore_rows[base + tid] : -1;
    __syncthreads();

    for (int f = tid; f < RW * 16; f += 256) {
        int rw = f >> 4, j = f & 15;
        int r = s_rows[rw];
        if (r >= 0)
            *(float4*)(s_zrow + rw * 64 + j * 4) = ((const float4*)z)[(size_t)r * 16 + j];
    }
    __syncthreads();

    int rowA = s_rows[w], rowB = s_rows[w + 8];

    float zzA = 0.f, zzB = 0.f;
    if (rowA >= 0) for (int i = 0; i < 64; ++i) { float v = s_zrow[w * 64 + i]; zzA += v * v; }
    if (rowB >= 0) for (int i = 0; i < 64; ++i) { float v = s_zrow[(w + 8) * 64 + i]; zzB += v * v; }

    float dmA = 3.4e38f, dmB = 3.4e38f;
    int   bA = 0, bB = 0;

    for (int tt = 0; tt < K / 128; ++tt) {
        __syncthreads();
        for (int f = tid; f < 128 * 16; f += 256) {
            int e = f >> 4, j = f & 15;
            float4 v = ((const float4*)emb)[(size_t)(tt * 128 + e) * 16 + j];
            float* dst = s_emb + e * 69 + j * 4;
            dst[0] = v.x; dst[1] = v.y; dst[2] = v.z; dst[3] = v.w;
        }
        __syncthreads();
        #pragma unroll
        for (int s = 0; s < 4; ++s) {
            int el = s * 32 + l;
            const float* e = s_emb + el * 69;
            int ge = tt * 128 + el;
            float eev = g_ee[ge];
            if (rowA >= 0) {
                float ze = 0.f;
                for (int i = 0; i < 64; ++i) ze += s_zrow[w * 64 + i] * e[i];
                float d = (zzA - 2.0f * ze) + eev;
                if (d < dmA) { dmA = d; bA = ge; }
            }
            if (rowB >= 0) {
                float ze = 0.f;
                for (int i = 0; i < 64; ++i) ze += s_zrow[(w + 8) * 64 + i] * e[i];
                float d = (zzB - 2.0f * ze) + eev;
                if (d < dmB) { dmB = d; bB = ge; }
            }
        }
    }

    #pragma unroll
    for (int off = 16; off; off >>= 1) {
        float od = __shfl_down_sync(0xffffffffu, dmA, off);
        int   oi = __shfl_down_sync(0xffffffffu, bA, off);
        if (od < dmA || (od == dmA && oi < bA)) { dmA = od; bA = oi; }
        float od2 = __shfl_down_sync(0xffffffffu, dmB, off);
        int   oi2 = __shfl_down_sync(0xffffffffu, bB, off);
        if (od2 < dmB || (od2 == dmB && oi2 < bB)) { dmB = od2; bB = oi2; }
    }

    if (l == 0) {
        double lacc = 0.0;
        if (rowA >= 0) {
            const float4* eb = (const float4*)emb + (size_t)bA * 16;
            float4* op = (float4*)out + (size_t)rowA * 16;
            for (int j = 0; j < 16; ++j) {
                float4 q = eb[j];
                float zx = s_zrow[w * 64 + j * 4 + 0];
                float zy = s_zrow[w * 64 + j * 4 + 1];
                float zzv = s_zrow[w * 64 + j * 4 + 2];
                float zw = s_zrow[w * 64 + j * 4 + 3];
                op[j] = q;
                float dx = q.x - zx, dy = q.y - zy, dz = q.z - zzv, dw = q.w - zw;
                lacc += (double)dx * dx + (double)dy * dy
                      + (double)dz * dz + (double)dw * dw;
            }
        }
        if (rowB >= 0) {
            const float4* eb = (const float4*)emb + (size_t)bB * 16;
            float4* op = (float4*)out + (size_t)rowB * 16;
            for (int j = 0; j < 16; ++j) {
                float4 q = eb[j];
                float zx = s_zrow[(w + 8) * 64 + j * 4 + 0];
                float zy = s_zrow[(w + 8) * 64 + j * 4 + 1];
                float zzv = s_zrow[(w + 8) * 64 + j * 4 + 2];
                float zw = s_zrow[(w + 8) * 64 + j * 4 + 3];
                op[j] = q;
                float dx = q.x - zx, dy = q.y - zy, dz = q.z - zzv, dw = q.w - zw;
                lacc += (double)dx * dx + (double)dy * dy
                      + (double)dz * dz + (double)dw * dw;
            }
        }
        if (lacc != 0.0) atomicAdd(&g_acc, lacc);
    }
}

__global__ void vq_fin_kernel(float* __restrict__ out, int out_size) {
    if (out_size > NROWS * D) {
        out[NROWS * D] = (float)(1.25 * g_acc / (double)((long long)NROWS * D));
    }
}

extern "C" void kernel_launch(void* const* d_in, const int* in_sizes, int n_in,
                              void* d_out, int out_size) {
    const float* z   = (const float*)d_in[0];
    const float* emb = (const float*)d_in[1];
    if (n_in >= 2 && in_sizes[0] == K * D && in_sizes[1] == NROWS * D) {
        z   = (const float*)d_in[1];
        emb = (const float*)d_in[0];
    }
    float* out = (float*)d_out;

    vq_pre_emb_kernel<<<8, 128>>>(emb);
    vq_pre_z_kernel<<<NROWS / 256, 256>>>(z);
    vq_main_kernel<<<NCTAS, BLOCK>>>(z, emb, out);
    vq_rescore_kernel<<<NROWS / RW, 256>>>(z, emb, out);
    vq_fin_kernel<<<1, 1>>>(out, out_size);
}

// round 15
// speedup vs baseline: 2.1919x; 1.0283x over previous
#include <cuda_runtime.h>
#include <cstdint>

#define NROWS 65536
#define D 64
#define K 1024
#define BLOCK 256
#define NCTAS (NROWS / BLOCK)   // 256
#define CH 256
#define NCH (K / CH)            // 4
#define TAU 5e-4f
#define RW 16
#define RBLOCKS 512
#define SE 130048.0f            // 127*1024

// Static scratch (no allocations). g_done starts 0; reset by last rescore block.
__device__ uint4  g_emb8[K * 4];
__device__ float  g_ee[K];
__device__ uint4  g_z8[NROWS * 4];
__device__ float  g_isz[NROWS];
__device__ double g_acc;
__device__ int    g_rescore_n;
__device__ int    g_rescore_rows[NROWS];
__device__ int    g_done;

__device__ __forceinline__ uint32_t pk4(int a, int b, int c, int d) {
    return (uint32_t)(a & 255) | ((uint32_t)(b & 255) << 8) |
           ((uint32_t)(c & 255) << 16) | ((uint32_t)(d & 255) << 24);
}
__device__ __forceinline__ void imma16832(int& c0, int& c1, int& c2, int& c3,
                                          uint32_t a0, uint32_t a1, uint32_t a2, uint32_t a3,
                                          uint32_t b0, uint32_t b1) {
    asm volatile("mma.sync.aligned.m16n8k32.row.col.s32.s8.s8.s32 "
                 "{%0,%1,%2,%3}, {%4,%5,%6,%7}, {%8,%9}, {%0,%1,%2,%3};"
                 : "+r"(c0), "+r"(c1), "+r"(c2), "+r"(c3)
                 : "r"(a0), "r"(a1), "r"(a2), "r"(a3), "r"(b0), "r"(b1));
}
__device__ __forceinline__ float packd(float d, uint32_t e) {
    return __uint_as_float((__float_as_uint(d) & 0xFFFFFC00u) | e);
}
__device__ __forceinline__ void upd4(float& m1, float& m2, float& m3, float& m4, float f) {
    float x1 = fmaxf(m1, f); m1 = fminf(m1, f);
    float x2 = fmaxf(m2, x1); m2 = fminf(m2, x1);
    float x3 = fmaxf(m3, x2); m3 = fminf(m3, x2);
    m4 = fminf(m4, x3);
}
__device__ __forceinline__ void red4x4(float& m1, float& m2, float& m3, float& m4) {
    #pragma unroll
    for (int off = 1; off <= 2; off <<= 1) {
        float o1 = __shfl_xor_sync(0xffffffffu, m1, off);
        float o2 = __shfl_xor_sync(0xffffffffu, m2, off);
        float o3 = __shfl_xor_sync(0xffffffffu, m3, off);
        float o4 = __shfl_xor_sync(0xffffffffu, m4, off);
        float n1 = fminf(m1, o1);
        float n2 = fminf(fminf(m2, o2), fmaxf(m1, o1));
        float n3 = fminf(fminf(m3, o3), fminf(fmaxf(m2, o1), fmaxf(m1, o2)));
        float n4 = fminf(fminf(m4, o4),
                   fminf(fminf(fmaxf(m3, o1), fmaxf(m1, o3)), fmaxf(m2, o2)));
        m1 = n1; m2 = n2; m3 = n3; m4 = n4;
    }
}

// Merged prep: emb quant + ||e||^2 (threads with r<K) and z quant (all rows).
__global__ __launch_bounds__(256)
void vq_pre_kernel(const float* __restrict__ z, const float* __restrict__ emb) {
    int r = blockIdx.x * blockDim.x + threadIdx.x;
    if (r == 0) { g_acc = 0.0; g_rescore_n = 0; }
    if (r < K) {
        const float* e = emb + r * D;
        float s = 0.f;
        int q[64];
        #pragma unroll
        for (int j = 0; j < 64; ++j) {
            float v = e[j];
            s += v * v;
            q[j] = __float2int_rn(v * SE);
        }
        g_ee[r] = s;
        #pragma unroll
        for (int t = 0; t < 4; ++t) {
            uint4 d;
            d.x = pk4(q[4*t],    q[4*t+1],    q[4*t+2],    q[4*t+3]);
            d.y = pk4(q[16+4*t], q[16+4*t+1], q[16+4*t+2], q[16+4*t+3]);
            d.z = pk4(q[32+4*t], q[32+4*t+1], q[32+4*t+2], q[32+4*t+3]);
            d.w = pk4(q[48+4*t], q[48+4*t+1], q[48+4*t+2], q[48+4*t+3]);
            g_emb8[r * 4 + t] = d;
        }
    }
    // z row prep
    const float4* zp = (const float4*)z + (size_t)r * 16;
    float v[64];
    float m = 0.f;
    #pragma unroll
    for (int j = 0; j < 16; ++j) {
        float4 u = zp[j];
        v[4*j] = u.x; v[4*j+1] = u.y; v[4*j+2] = u.z; v[4*j+3] = u.w;
        m = fmaxf(m, fmaxf(fmaxf(fabsf(u.x), fabsf(u.y)),
                           fmaxf(fabsf(u.z), fabsf(u.w))));
    }
    m = fmaxf(m, 1e-20f);
    float sz = 127.f / m;
    g_isz[r] = 2.f * m / (127.f * SE);
    int q[64];
    #pragma unroll
    for (int j = 0; j < 64; ++j) q[j] = __float2int_rn(v[j] * sz);
    #pragma unroll
    for (int t = 0; t < 4; ++t) {
        uint4 d;
        d.x = pk4(q[4*t],    q[4*t+1],    q[4*t+2],    q[4*t+3]);
        d.y = pk4(q[16+4*t], q[16+4*t+1], q[16+4*t+2], q[16+4*t+3]);
        d.z = pk4(q[32+4*t], q[32+4*t+1], q[32+4*t+2], q[32+4*t+3]);
        d.w = pk4(q[48+4*t], q[48+4*t+1], q[48+4*t+2], q[48+4*t+3]);
        g_z8[r * 4 + t] = d;
    }
}

__device__ __forceinline__ float exact_d(const float4* zp, const float* __restrict__ emb,
                                         float zz, float eek, int idx) {
    const float4* ev = (const float4*)(emb + (size_t)idx * D);
    float ze = 0.f;
    #pragma unroll
    for (int j = 0; j < 16; ++j) {
        float4 e = ev[j];
        float4 zv = zp[j];
        ze += zv.x * e.x; ze += zv.y * e.y;
        ze += zv.z * e.z; ze += zv.w * e.w;
    }
    return (zz - 2.0f * ze) + eek;
}

__global__ __launch_bounds__(BLOCK)
void vq_main_kernel(const float* __restrict__ z,
                    const float* __restrict__ emb,
                    float* __restrict__ out) {
    __shared__ uint4  s_b[CH * 4];
    __shared__ float  s_ee[K];
    __shared__ float  s_m1[BLOCK], s_m2[BLOCK], s_m3[BLOCK], s_m4[BLOCK];
    __shared__ double s_red[BLOCK / 32];

    const int tid   = threadIdx.x;
    const int warp  = tid >> 5;
    const int lane  = tid & 31;
    const int g     = lane >> 2;
    const int t     = lane & 3;
    const int rbase = blockIdx.x * BLOCK;
    const int wrow  = rbase + warp * 32;

    #pragma unroll
    for (int i = 0; i < K / BLOCK; ++i)
        s_ee[i * BLOCK + tid] = g_ee[i * BLOCK + tid];

    uint4 Q0 = g_z8[(size_t)(wrow + g) * 4 + t];
    uint4 Q1 = g_z8[(size_t)(wrow + g + 8) * 4 + t];
    uint4 Q2 = g_z8[(size_t)(wrow + g + 16) * 4 + t];
    uint4 Q3 = g_z8[(size_t)(wrow + g + 24) * 4 + t];
    float isz0 = g_isz[wrow + g];
    float isz1 = g_isz[wrow + g + 8];
    float isz2 = g_isz[wrow + g + 16];
    float isz3 = g_isz[wrow + g + 24];

    float a1 = 3.0e38f, a2 = 3.0e38f, a3 = 3.0e38f, a4 = 3.0e38f;
    float b1 = 3.0e38f, b2 = 3.0e38f, b3 = 3.0e38f, b4 = 3.0e38f;
    float c1 = 3.0e38f, c2 = 3.0e38f, c3 = 3.0e38f, c4 = 3.0e38f;
    float d1 = 3.0e38f, d2 = 3.0e38f, d3 = 3.0e38f, d4 = 3.0e38f;

    for (int ch = 0; ch < NCH; ++ch) {
        __syncthreads();
        {
            const uint4* src = g_emb8 + (size_t)(ch * CH + tid) * 4;
            uint4* dst = s_b + tid * 4;
            dst[0] = src[0]; dst[1] = src[1]; dst[2] = src[2]; dst[3] = src[3];
        }
        __syncthreads();

        for (int nt = 0; nt < CH / 8; ++nt) {
            const int nbl = nt * 8;
            const int nb  = ch * CH + nbl;
            uint4 E = s_b[(nbl + g) * 4 + t];

            int c00 = 0, c01 = 0, c02 = 0, c03 = 0;
            int c10 = 0, c11 = 0, c12 = 0, c13 = 0;
            imma16832(c00, c01, c02, c03, Q0.x, Q1.x, Q0.y, Q1.y, E.x, E.y);
            imma16832(c00, c01, c02, c03, Q0.z, Q1.z, Q0.w, Q1.w, E.z, E.w);
            imma16832(c10, c11, c12, c13, Q2.x, Q3.x, Q2.y, Q3.y, E.x, E.y);
            imma16832(c10, c11, c12, c13, Q2.z, Q3.z, Q2.w, Q3.w, E.z, E.w);

            float2 ee = *(const float2*)(s_ee + nb + 2 * t);
            uint32_t e0 = nb + 2 * t, e1 = e0 + 1;
            upd4(a1, a2, a3, a4, packd(fmaf(-isz0, (float)c00, ee.x), e0));
            upd4(a1, a2, a3, a4, packd(fmaf(-isz0, (float)c01, ee.y), e1));
            upd4(b1, b2, b3, b4, packd(fmaf(-isz1, (float)c02, ee.x), e0));
            upd4(b1, b2, b3, b4, packd(fmaf(-isz1, (float)c03, ee.y), e1));
            upd4(c1, c2, c3, c4, packd(fmaf(-isz2, (float)c10, ee.x), e0));
            upd4(c1, c2, c3, c4, packd(fmaf(-isz2, (float)c11, ee.y), e1));
            upd4(d1, d2, d3, d4, packd(fmaf(-isz3, (float)c12, ee.x), e0));
            upd4(d1, d2, d3, d4, packd(fmaf(-isz3, (float)c13, ee.y), e1));
        }
    }

    red4x4(a1, a2, a3, a4); red4x4(b1, b2, b3, b4);
    red4x4(c1, c2, c3, c4); red4x4(d1, d2, d3, d4);
    if (t == 0) {
        int lr = warp * 32 + g;
        s_m1[lr]      = a1; s_m2[lr]      = a2; s_m3[lr]      = a3; s_m4[lr]      = a4;
        s_m1[lr + 8]  = b1; s_m2[lr + 8]  = b2; s_m3[lr + 8]  = b3; s_m4[lr + 8]  = b4;
        s_m1[lr + 16] = c1; s_m2[lr + 16] = c2; s_m3[lr + 16] = c3; s_m4[lr + 16] = c4;
        s_m1[lr + 24] = d1; s_m2[lr + 24] = d2; s_m3[lr + 24] = d3; s_m4[lr + 24] = d4;
    }
    __syncthreads();

    const int row = rbase + tid;
    float m1 = s_m1[tid], m2 = s_m2[tid], m3 = s_m3[tid], m4 = s_m4[tid];
    const float4* zp = (const float4*)z + (size_t)row * 16;

    int winner = -1;
    if (m2 - m1 >= TAU) {
        winner = (int)(__float_as_uint(m1) & 1023u);
    } else if (m4 - m1 >= TAU) {
        int i1 = (int)(__float_as_uint(m1) & 1023u);
        int i2 = (int)(__float_as_uint(m2) & 1023u);
        int i3 = (int)(__float_as_uint(m3) & 1023u);
        float zz = 0.f;
        #pragma unroll
        for (int j = 0; j < 16; ++j) {
            float4 zv = zp[j];
            zz += zv.x * zv.x; zz += zv.y * zv.y;
            zz += zv.z * zv.z; zz += zv.w * zv.w;
        }
        float e1 = exact_d(zp, emb, zz, s_ee[i1], i1);
        float e2 = exact_d(zp, emb, zz, s_ee[i2], i2);
        float e3 = exact_d(zp, emb, zz, s_ee[i3], i3);
        winner = i1; float wd = e1;
        if (e2 < wd || (e2 == wd && i2 < winner)) { wd = e2; winner = i2; }
        if (e3 < wd || (e3 == wd && i3 < winner)) { wd = e3; winner = i3; }
    }

    double lacc = 0.0;
    if (winner < 0) {
        int pos = atomicAdd(&g_rescore_n, 1);
        g_rescore_rows[pos] = row;
    } else {
        const float4* eb = (const float4*)emb + (size_t)winner * 16;
        float4* op = (float4*)out + (size_t)row * 16;
        #pragma unroll
        for (int j = 0; j < 16; ++j) {
            float4 q = eb[j];
            float4 zv = zp[j];
            op[j] = q;
            float dx = q.x - zv.x, dy = q.y - zv.y;
            float dz = q.z - zv.z, dw = q.w - zv.w;
            lacc += (double)dx * dx + (double)dy * dy
                  + (double)dz * dz + (double)dw * dw;
        }
    }
    #pragma unroll
    for (int off = 16; off; off >>= 1)
        lacc += __shfl_down_sync(0xffffffffu, lacc, off);
    if (lane == 0) s_red[warp] = lacc;
    __syncthreads();
    if (tid == 0) {
        double b = 0.0;
        #pragma unroll
        for (int i = 0; i < BLOCK / 32; ++i) b += s_red[i];
        atomicAdd(&g_acc, b);
    }
}

// Exact fp32 full rescan: 512 blocks x 512 thr, slice loop, double-buffered tiles.
__global__ __launch_bounds__(512)
void vq_rescore_fin_kernel(const float* __restrict__ z,
                           const float* __restrict__ emb,
                           float* __restrict__ out, int out_size) {
    __shared__ float s_emb[128 * 69];    // 35.3 KB fp32 tile, ld=69 (conflict-free)
    __shared__ float s_zrow[RW * 64];
    __shared__ int   s_rows[RW];
    __shared__ double s_red[16];
    __shared__ int   s_last;

    const int nre = g_rescore_n;
    const int tid = threadIdx.x;
    const int w = tid >> 5, l = tid & 31;   // 16 warps, 1 row/warp

    // Thread -> 4 (entry, j) slots for tile staging.
    int e0s = tid >> 4,          j0s = tid & 15;
    int e1s = (tid + 512) >> 4,  j1s = j0s;
    int e2s = (tid + 1024) >> 4, j2s = j0s;
    int e3s = (tid + 1536) >> 4, j3s = j0s;

    double wacc = 0.0;
    for (int base = blockIdx.x * RW; base < nre; base += RBLOCKS * RW) {
        __syncthreads();
        if (tid < RW)
            s_rows[tid] = (base + tid < nre) ? g_rescore_rows[base + tid] : -1;
        __syncthreads();
        if (tid < RW * 16) {
            int rw = tid >> 4, j = tid & 15;
            int r = s_rows[rw];
            if (r >= 0)
                *(float4*)(s_zrow + rw * 64 + j * 4) = ((const float4*)z)[(size_t)r * 16 + j];
        }

        const int myrow = s_rows[w];
        float zz = 0.f;
        float dmin = 3.4e38f;
        int   best = 0;

        // Prefetch tile 0.
        float4 pf0 = ((const float4*)emb)[(size_t)e0s * 16 + j0s];
        float4 pf1 = ((const float4*)emb)[(size_t)e1s * 16 + j1s];
        float4 pf2 = ((const float4*)emb)[(size_t)e2s * 16 + j2s];
        float4 pf3 = ((const float4*)emb)[(size_t)e3s * 16 + j3s];
        __syncthreads();
        if (myrow >= 0)
            for (int i = 0; i < 64; ++i) { float v = s_zrow[w * 64 + i]; zz += v * v; }

        for (int tt = 0; tt < 8; ++tt) {
            // Store prefetched tile as SCALAR stores (ld=69 is not float4-aligned).
            float* d0 = s_emb + e0s * 69 + j0s * 4;
            d0[0] = pf0.x; d0[1] = pf0.y; d0[2] = pf0.z; d0[3] = pf0.w;
            float* d1p = s_emb + e1s * 69 + j1s * 4;
            d1p[0] = pf1.x; d1p[1] = pf1.y; d1p[2] = pf1.z; d1p[3] = pf1.w;
            float* d2p = s_emb + e2s * 69 + j2s * 4;
            d2p[0] = pf2.x; d2p[1] = pf2.y; d2p[2] = pf2.z; d2p[3] = pf2.w;
            float* d3p = s_emb + e3s * 69 + j3s * 4;
            d3p[0] = pf3.x; d3p[1] = pf3.y; d3p[2] = pf3.z; d3p[3] = pf3.w;
            __syncthreads();
            // Issue next tile's loads (hidden under the scan below).
            if (tt < 7) {
                size_t nb = (size_t)(tt + 1) * 128 * 16;
                pf0 = ((const float4*)emb)[nb + e0s * 16 + j0s];
                pf1 = ((const float4*)emb)[nb + e1s * 16 + j1s];
                pf2 = ((const float4*)emb)[nb + e2s * 16 + j2s];
                pf3 = ((const float4*)emb)[nb + e3s * 16 + j3s];
            }
            if (myrow >= 0) {
                #pragma unroll
                for (int s = 0; s < 4; ++s) {
                    int el = s * 32 + l;
                    const float* e = s_emb + el * 69;
                    float ze = 0.f;
                    for (int i = 0; i < 64; ++i) ze += s_zrow[w * 64 + i] * e[i];
                    int ge = tt * 128 + el;
                    float d = (zz - 2.0f * ze) + g_ee[ge];
                    if (d < dmin) { dmin = d; best = ge; }
                }
            }
            __syncthreads();
        }

        #pragma unroll
        for (int off = 16; off; off >>= 1) {
            float od = __shfl_down_sync(0xffffffffu, dmin, off);
            int   oi = __shfl_down_sync(0xffffffffu, best, off);
            if (od < dmin || (od == dmin && oi < best)) { dmin = od; best = oi; }
        }

        if (myrow >= 0 && l == 0) {
            const float4* eb = (const float4*)emb + (size_t)best * 16;
            float4* op = (float4*)out + (size_t)myrow * 16;
            for (int j = 0; j < 16; ++j) {
                float4 q = eb[j];
                float zx = s_zrow[w * 64 + j * 4 + 0];
                float zy = s_zrow[w * 64 + j * 4 + 1];
                float zzv = s_zrow[w * 64 + j * 4 + 2];
                float zw = s_zrow[w * 64 + j * 4 + 3];
                op[j] = q;
                float dx = q.x - zx, dy = q.y - zy, dz = q.z - zzv, dw = q.w - zw;
                wacc += (double)dx * dx + (double)dy * dy
                      + (double)dz * dz + (double)dw * dw;
            }
        }
    }

    __syncthreads();
    if (l == 0) s_red[w] = wacc;
    __syncthreads();
    if (tid == 0) {
        double s2 = 0.0;
        #pragma unroll
        for (int i = 0; i < 16; ++i) s2 += s_red[i];
        if (s2 != 0.0) atomicAdd(&g_acc, s2);
        __threadfence();
        s_last = (atomicAdd(&g_done, 1) == RBLOCKS - 1);
    }
    __syncthreads();
    if (s_last && tid == 0) {
        if (out_size > NROWS * D)
            out[NROWS * D] = (float)(1.25 * g_acc / (double)((long long)NROWS * D));
        g_done = 0;   // reset for next graph replay
    }
}

extern "C" void kernel_launch(void* const* d_in, const int* in_sizes, int n_in,
                              void* d_out, int out_size) {
    const float* z   = (const float*)d_in[0];
    const float* emb = (const float*)d_in[1];
    if (n_in >= 2 && in_sizes[0] == K * D && in_sizes[1] == NROWS * D) {
        z   = (const float*)d_in[1];
        emb = (const float*)d_in[0];
    }
    float* out = (float*)d_out;

    vq_pre_kernel<<<NROWS / 256, 256>>>(z, emb);
    vq_main_kernel<<<NCTAS, BLOCK>>>(z, emb, out);
    vq_rescore_fin_kernel<<<RBLOCKS, 512>>>(z, emb, out, out_size);
}